// round 3
// baseline (speedup 1.0000x reference)
#include <cuda_runtime.h>

#define NROWS 256
#define NDB   100000
#define DIM   64
#define XDIM  2048
#define NCLS  100
#define KSEL  1000

// ---------------- static device scratch (no allocations allowed) ----------------
__device__ float              g_outm[NROWS * DIM];                      // 64 KB
__device__ unsigned int       g_S[(size_t)NROWS * NDB];                 // 102.4 MB (monotone keys)
__device__ unsigned long long g_cand[(size_t)NROWS * NDB];              // 204.8 MB (worst-case candidates)
__device__ int                g_d1[NROWS];
__device__ int                g_need[NROWS];
__device__ unsigned int       g_candCnt[NROWS];
__device__ unsigned int       g_counts[NROWS * NCLS];

// ---------------- helpers ----------------
__device__ __forceinline__ unsigned int mkey(float f) {
    unsigned int u = __float_as_uint(f);
    return (u & 0x80000000u) ? ~u : (u | 0x80000000u);   // larger float -> larger key
}

__device__ __forceinline__ unsigned long long pk(float lo, float hi) {
    unsigned long long r;
    asm("mov.b64 %0, {%1,%2};" : "=l"(r)
        : "r"(__float_as_uint(lo)), "r"(__float_as_uint(hi)));
    return r;
}
__device__ __forceinline__ float f32lo(unsigned long long v) {
    return __uint_as_float((unsigned int)v);
}
__device__ __forceinline__ float f32hi(unsigned long long v) {
    return __uint_as_float((unsigned int)(v >> 32));
}
__device__ __forceinline__ void fma2(unsigned long long& d, unsigned long long a, unsigned long long b) {
    asm("fma.rn.f32x2 %0, %1, %2, %0;" : "+l"(d) : "l"(a), "l"(b));
}

// labels dtype probe: if the buffer is int64, the odd 32-bit words (high words
// of values < 100) are all zero. For genuine int32 labels (uniform in [0,100))
// the chance all 64 sampled odd words are zero is 100^-64.
__device__ __forceinline__ int probe_is64(const int* L) {
    int s = 0;
#pragma unroll
    for (int i = 1; i < 129; i += 2) s |= L[i];
    return (s == 0) ? 1 : 0;
}
__device__ __forceinline__ int ldlabel(const int* L, int n, int is64) {
    return is64 ? L[(size_t)2 * n] : L[n];
}

// ---------------- K1: out = x @ W  (256x2048 @ 2048x64), 16-way tree accumulation ----------------
__global__ void __launch_bounds__(256) k1_proj(const float* __restrict__ x,
                                               const float* __restrict__ W) {
    __shared__ __align__(16) float xs[XDIM];
    __shared__ float part[4][DIM];
    int b = blockIdx.x;
    const float4* xr = (const float4*)(x + (size_t)b * XDIM);
    for (int i = threadIdx.x; i < XDIM / 4; i += 256)
        ((float4*)xs)[i] = xr[i];
    __syncthreads();

    int j = threadIdx.x & 63;
    int p = threadIdx.x >> 6;
    const float* Wp = W + (size_t)(p * 512) * DIM + j;
    const float* xp = xs + p * 512;
    float a0 = 0.f, a1 = 0.f, a2 = 0.f, a3 = 0.f;
#pragma unroll 4
    for (int k = 0; k < 128; k++) {
        a0 += xp[k]       * Wp[(size_t)(k)       * DIM];
        a1 += xp[k + 128] * Wp[(size_t)(k + 128) * DIM];
        a2 += xp[k + 256] * Wp[(size_t)(k + 256) * DIM];
        a3 += xp[k + 384] * Wp[(size_t)(k + 384) * DIM];
    }
    part[p][j] = (a0 + a1) + (a2 + a3);
    __syncthreads();
    if (threadIdx.x < DIM)
        g_outm[b * DIM + threadIdx.x] =
            (part[0][threadIdx.x] + part[1][threadIdx.x]) +
            (part[2][threadIdx.x] + part[3][threadIdx.x]);
}

// ---------------- K2: S-keys = mkey(out @ codes^T), tiles 64x128, f32x2 FMA ----------------
__global__ void __launch_bounds__(256, 3) k2_gemm(const float* __restrict__ codes) {
    __shared__ __align__(16) float As[64 * 64];    // k-major, 2-elem group XOR swizzle
    __shared__ __align__(16) float Bs[64 * 128];   // k-major, 4-elem group XOR swizzle
    const int tid  = threadIdx.x;
    const int row0 = blockIdx.y << 6;
    const int col0 = blockIdx.x << 7;

    // load A tile (64 rows x 64 k), transpose to k-major with swizzle
#pragma unroll
    for (int t = 0; t < 4; t++) {
        int e  = tid + t * 256;          // 0..1023
        int i  = e >> 4;                 // row in tile
        int k4 = (e & 15) << 2;          // k base
        float4 v = *(const float4*)&g_outm[((row0 + i) << 6) + k4];
#pragma unroll
        for (int j = 0; j < 4; j++) {
            int k = k4 + j;
            As[(k << 6) + ((((i >> 1) ^ (k & 31)) << 1) | (i & 1))] = (&v.x)[j];
        }
    }
    // load B tile (128 cols x 64 k), transpose to k-major with swizzle
#pragma unroll
    for (int t = 0; t < 8; t++) {
        int e  = tid + t * 256;          // 0..2047
        int n  = e >> 4;                 // col in tile
        int k4 = (e & 15) << 2;
        int gn = col0 + n;
        float4 v = make_float4(0.f, 0.f, 0.f, 0.f);
        if (gn < NDB) v = *(const float4*)&codes[((size_t)gn << 6) + k4];
#pragma unroll
        for (int j = 0; j < 4; j++) {
            int k = k4 + j;
            Bs[(k << 7) + ((((n >> 2) ^ (k & 31)) << 2) | (n & 3))] = (&v.x)[j];
        }
    }
    __syncthreads();

    const int r = tid >> 5;   // 0..7  : 8 rows each (4 row-pairs)
    const int c = tid & 31;   // 0..31 : 4 cols each
    unsigned long long acc[4][4];
#pragma unroll
    for (int p = 0; p < 4; p++)
#pragma unroll
        for (int j = 0; j < 4; j++) acc[p][j] = 0ull;

#pragma unroll 4
    for (int k = 0; k < 64; k++) {
        int kb = k & 31;
        float4 bv = *(const float4*)&Bs[(k << 7) + ((c ^ kb) << 2)];
        unsigned long long b0 = pk(bv.x, bv.x);
        unsigned long long b1 = pk(bv.y, bv.y);
        unsigned long long b2 = pk(bv.z, bv.z);
        unsigned long long b3 = pk(bv.w, bv.w);
#pragma unroll
        for (int p = 0; p < 4; p++) {
            int grp = (r << 2) + p;   // (r*8 + 2p) >> 1
            float2 a = *(const float2*)&As[(k << 6) + ((grp ^ kb) << 1)];
            unsigned long long av = pk(a.x, a.y);
            fma2(acc[p][0], av, b0);
            fma2(acc[p][1], av, b1);
            fma2(acc[p][2], av, b2);
            fma2(acc[p][3], av, b3);
        }
    }

    int ncol = col0 + (c << 2);
    if (ncol < NDB) {
#pragma unroll
        for (int p = 0; p < 4; p++) {
            int rowA = row0 + (r << 3) + (p << 1);
            uint4 lo, hi;
            lo.x = mkey(f32lo(acc[p][0])); hi.x = mkey(f32hi(acc[p][0]));
            lo.y = mkey(f32lo(acc[p][1])); hi.y = mkey(f32hi(acc[p][1]));
            lo.z = mkey(f32lo(acc[p][2])); hi.z = mkey(f32hi(acc[p][2]));
            lo.w = mkey(f32lo(acc[p][3])); hi.w = mkey(f32hi(acc[p][3]));
            *(uint4*)&g_S[(size_t)rowA * NDB + ncol]       = lo;
            *(uint4*)&g_S[(size_t)(rowA + 1) * NDB + ncol] = hi;
        }
    }
}

// ---------------- K3: per-row 4096-bin histogram on key[31:20]; pick boundary bin ----------------
__global__ void __launch_bounds__(512) k3_hist() {
    __shared__ unsigned int h[4096];
    int b = blockIdx.x;
    for (int i = threadIdx.x; i < 4096; i += 512) h[i] = 0u;
    __syncthreads();
    const uint4* Sp = (const uint4*)&g_S[(size_t)b * NDB];
    for (int i = threadIdx.x; i < NDB / 4; i += 512) {
        uint4 v = Sp[i];
        atomicAdd(&h[v.x >> 20], 1u);
        atomicAdd(&h[v.y >> 20], 1u);
        atomicAdd(&h[v.z >> 20], 1u);
        atomicAdd(&h[v.w >> 20], 1u);
    }
    __syncthreads();
    if (threadIdx.x == 0) {
        unsigned int cum = 0;
        int d = 4095;
        for (; d > 0; d--) {
            cum += h[d];
            if ((int)cum >= KSEL) break;
        }
        if ((int)cum < KSEL) cum += h[0];        // d == 0 fallthrough
        g_d1[b]   = d;
        g_need[b] = KSEL - (int)(cum - h[d]);
    }
}

// ---------------- K4: label-count strictly-above items; compact boundary-bin candidates ----------------
__global__ void __launch_bounds__(512) k4_compact(const int* __restrict__ labels) {
    __shared__ unsigned int lh[NCLS];
    __shared__ unsigned int cnt;
    __shared__ int s_is64;
    int b  = blockIdx.x;
    int d1 = g_d1[b];
    if (threadIdx.x < NCLS) lh[threadIdx.x] = 0u;
    if (threadIdx.x == 0) { cnt = 0u; s_is64 = probe_is64(labels); }
    __syncthreads();
    int is64 = s_is64;

    const unsigned int* Sp = &g_S[(size_t)b * NDB];
    unsigned long long* cp = &g_cand[(size_t)b * NDB];
    for (int n = threadIdx.x; n < NDB; n += 512) {
        unsigned int mk = Sp[n];
        int top = (int)(mk >> 20);
        if (top > d1) {
            int l = ldlabel(labels, n, is64);
            if (l >= 0 && l < NCLS) atomicAdd(&lh[l], 1u);
        } else if (top == d1) {
            unsigned int p = atomicAdd(&cnt, 1u);
            unsigned long long cval =
                ((unsigned long long)(mk & 0xFFFFFu) << 17) |
                (unsigned long long)(unsigned int)(131071 - n);
            cp[p] = cval;
        }
    }
    __syncthreads();
    if (threadIdx.x < NCLS) g_counts[b * NCLS + threadIdx.x] = lh[threadIdx.x];
    if (threadIdx.x == 0) g_candCnt[b] = cnt;
}

// ---------------- K5: exact 3-stage radix select on 37-bit composite; finalize probs ----------------
__global__ void __launch_bounds__(512) k5_select(const int* __restrict__ labels,
                                                 float* __restrict__ out) {
    __shared__ unsigned int h[8192];
    __shared__ unsigned int lh[NCLS];
    __shared__ int s_dig, s_need, s_is64;
    int b = blockIdx.x;
    int need = g_need[b];
    unsigned int cc = g_candCnt[b];
    const unsigned long long* cp = &g_cand[(size_t)b * NDB];

    if (threadIdx.x == 0) s_is64 = probe_is64(labels);

    const int shifts[3] = {24, 12, 0};
    const int nbits[3]  = {13, 12, 12};
    unsigned long long prefix = 0ull;

    for (int s = 0; s < 3; s++) {
        int sh = shifts[s];
        int nb = 1 << nbits[s];
        unsigned long long pmask = ~(((1ull << (sh + nbits[s])) - 1ull));
        for (int i = threadIdx.x; i < nb; i += 512) h[i] = 0u;
        __syncthreads();
        for (unsigned int i = threadIdx.x; i < cc; i += 512) {
            unsigned long long cv = cp[i];
            if ((cv & pmask) == prefix)
                atomicAdd(&h[(unsigned int)(cv >> sh) & (nb - 1)], 1u);
        }
        __syncthreads();
        if (threadIdx.x == 0) {
            unsigned int cum = 0;
            int d = nb - 1;
            for (; d > 0; d--) {
                cum += h[d];
                if ((int)cum >= need) break;
            }
            if ((int)cum < need) cum += h[0];
            s_dig  = d;
            s_need = need - (int)(cum - h[d]);
        }
        __syncthreads();
        prefix |= ((unsigned long long)s_dig) << sh;
        need = s_need;
        __syncthreads();
    }
    // prefix is now the exact K-th composite key (unique); select cv >= prefix.

    if (threadIdx.x < NCLS) lh[threadIdx.x] = 0u;
    __syncthreads();
    int is64 = s_is64;
    for (unsigned int i = threadIdx.x; i < cc; i += 512) {
        unsigned long long cv = cp[i];
        if (cv >= prefix) {
            int idx = 131071 - (int)(cv & 0x1FFFFull);
            if (idx >= 0 && idx < NDB) {
                int l = ldlabel(labels, idx, is64);
                if (l >= 0 && l < NCLS) atomicAdd(&lh[l], 1u);
            }
        }
    }
    __syncthreads();
    if (threadIdx.x < NCLS) {
        unsigned int tot = g_counts[b * NCLS + threadIdx.x] + lh[threadIdx.x];
        out[b * NCLS + threadIdx.x] = (float)tot * (1.0f / (float)KSEL);
    }
}

// ---------------- launch ----------------
extern "C" void kernel_launch(void* const* d_in, const int* in_sizes, int n_in,
                              void* d_out, int out_size) {
    const float* x      = (const float*)d_in[0];
    const float* W      = (const float*)d_in[1];
    const float* codes  = (const float*)d_in[2];
    const int*   labels = (const int*)d_in[3];
    float*       out    = (float*)d_out;

    k1_proj<<<NROWS, 256>>>(x, W);
    dim3 g2((NDB + 127) / 128, NROWS / 64);
    k2_gemm<<<g2, 256>>>(codes);
    k3_hist<<<NROWS, 512>>>();
    k4_compact<<<NROWS, 512>>>(labels);
    k5_select<<<NROWS, 512>>>(labels, out);
}

// round 4
// speedup vs baseline: 3.2272x; 3.2272x over previous
#include <cuda_runtime.h>

#define NROWS 256
#define NDB   100000
#define DIM   64
#define XDIM  2048
#define NCLS  100
#define KSEL  1000
#define SPLIT 8
#define VPB   3125            // uint4 vectors per (row-part): 100000/4/8

// ---------------- static device scratch (no allocations allowed) ----------------
__device__ float              g_outm[NROWS * DIM];
__device__ unsigned int       g_S[(size_t)NROWS * NDB];                 // 102.4 MB keys
__device__ unsigned long long g_cand[(size_t)NROWS * NDB];              // candidates
__device__ unsigned int       g_hist[NROWS * 4096];                     // 4 MB per-row hist
__device__ int                g_d1[NROWS];
__device__ int                g_need[NROWS];
__device__ unsigned int       g_candCnt[NROWS];
__device__ unsigned int       g_counts[NROWS * NCLS];

// ---------------- helpers ----------------
__device__ __forceinline__ unsigned int mkey(float f) {
    unsigned int u = __float_as_uint(f);
    return (u & 0x80000000u) ? ~u : (u | 0x80000000u);
}
__device__ __forceinline__ unsigned long long pk(float lo, float hi) {
    unsigned long long r;
    asm("mov.b64 %0, {%1,%2};" : "=l"(r)
        : "r"(__float_as_uint(lo)), "r"(__float_as_uint(hi)));
    return r;
}
__device__ __forceinline__ float f32lo(unsigned long long v) { return __uint_as_float((unsigned int)v); }
__device__ __forceinline__ float f32hi(unsigned long long v) { return __uint_as_float((unsigned int)(v >> 32)); }
__device__ __forceinline__ void fma2(unsigned long long& d, unsigned long long a, unsigned long long b) {
    asm("fma.rn.f32x2 %0, %1, %2, %0;" : "+l"(d) : "l"(a), "l"(b));
}
__device__ __forceinline__ int probe_is64(const int* L) {
    int s = 0;
#pragma unroll
    for (int i = 1; i < 129; i += 2) s |= L[i];
    return (s == 0) ? 1 : 0;
}
__device__ __forceinline__ int ldlabel(const int* L, int n, int is64) {
    return is64 ? L[(size_t)2 * n] : L[n];
}

// ---------------- K1: out = x @ W ----------------
__global__ void __launch_bounds__(256) k1_proj(const float* __restrict__ x,
                                               const float* __restrict__ W) {
    __shared__ __align__(16) float xs[XDIM];
    __shared__ float part[4][DIM];
    int b = blockIdx.x;
    const float4* xr = (const float4*)(x + (size_t)b * XDIM);
    for (int i = threadIdx.x; i < XDIM / 4; i += 256)
        ((float4*)xs)[i] = xr[i];
    __syncthreads();
    int j = threadIdx.x & 63;
    int p = threadIdx.x >> 6;
    const float* Wp = W + (size_t)(p * 512) * DIM + j;
    const float* xp = xs + p * 512;
    float a0 = 0.f, a1 = 0.f, a2 = 0.f, a3 = 0.f;
#pragma unroll 4
    for (int k = 0; k < 128; k++) {
        a0 += xp[k]       * Wp[(size_t)(k)       * DIM];
        a1 += xp[k + 128] * Wp[(size_t)(k + 128) * DIM];
        a2 += xp[k + 256] * Wp[(size_t)(k + 256) * DIM];
        a3 += xp[k + 384] * Wp[(size_t)(k + 384) * DIM];
    }
    part[p][j] = (a0 + a1) + (a2 + a3);
    __syncthreads();
    if (threadIdx.x < DIM)
        g_outm[b * DIM + threadIdx.x] =
            (part[0][threadIdx.x] + part[1][threadIdx.x]) +
            (part[2][threadIdx.x] + part[3][threadIdx.x]);
}

// ---------------- K2: keys = mkey(out @ codes^T) ----------------
__global__ void __launch_bounds__(256, 3) k2_gemm(const float* __restrict__ codes) {
    __shared__ __align__(16) float As[64 * 64];
    __shared__ __align__(16) float Bs[64 * 128];
    const int tid  = threadIdx.x;
    const int row0 = blockIdx.y << 6;
    const int col0 = blockIdx.x << 7;
#pragma unroll
    for (int t = 0; t < 4; t++) {
        int e  = tid + t * 256;
        int i  = e >> 4;
        int k4 = (e & 15) << 2;
        float4 v = *(const float4*)&g_outm[((row0 + i) << 6) + k4];
#pragma unroll
        for (int j = 0; j < 4; j++) {
            int k = k4 + j;
            As[(k << 6) + ((((i >> 1) ^ (k & 31)) << 1) | (i & 1))] = (&v.x)[j];
        }
    }
#pragma unroll
    for (int t = 0; t < 8; t++) {
        int e  = tid + t * 256;
        int n  = e >> 4;
        int k4 = (e & 15) << 2;
        int gn = col0 + n;
        float4 v = make_float4(0.f, 0.f, 0.f, 0.f);
        if (gn < NDB) v = *(const float4*)&codes[((size_t)gn << 6) + k4];
#pragma unroll
        for (int j = 0; j < 4; j++) {
            int k = k4 + j;
            Bs[(k << 7) + ((((n >> 2) ^ (k & 31)) << 2) | (n & 3))] = (&v.x)[j];
        }
    }
    __syncthreads();

    const int r = tid >> 5;
    const int c = tid & 31;
    unsigned long long acc[4][4];
#pragma unroll
    for (int p = 0; p < 4; p++)
#pragma unroll
        for (int j = 0; j < 4; j++) acc[p][j] = 0ull;

#pragma unroll 4
    for (int k = 0; k < 64; k++) {
        int kb = k & 31;
        float4 bv = *(const float4*)&Bs[(k << 7) + ((c ^ kb) << 2)];
        unsigned long long b0 = pk(bv.x, bv.x);
        unsigned long long b1 = pk(bv.y, bv.y);
        unsigned long long b2 = pk(bv.z, bv.z);
        unsigned long long b3 = pk(bv.w, bv.w);
#pragma unroll
        for (int p = 0; p < 4; p++) {
            int grp = (r << 2) + p;
            float2 a = *(const float2*)&As[(k << 6) + ((grp ^ kb) << 1)];
            unsigned long long av = pk(a.x, a.y);
            fma2(acc[p][0], av, b0);
            fma2(acc[p][1], av, b1);
            fma2(acc[p][2], av, b2);
            fma2(acc[p][3], av, b3);
        }
    }

    int ncol = col0 + (c << 2);
    if (ncol < NDB) {
#pragma unroll
        for (int p = 0; p < 4; p++) {
            int rowA = row0 + (r << 3) + (p << 1);
            uint4 lo, hi;
            lo.x = mkey(f32lo(acc[p][0])); hi.x = mkey(f32hi(acc[p][0]));
            lo.y = mkey(f32lo(acc[p][1])); hi.y = mkey(f32hi(acc[p][1]));
            lo.z = mkey(f32lo(acc[p][2])); hi.z = mkey(f32hi(acc[p][2]));
            lo.w = mkey(f32lo(acc[p][3])); hi.w = mkey(f32hi(acc[p][3]));
            *(uint4*)&g_S[(size_t)rowA * NDB + ncol]       = lo;
            *(uint4*)&g_S[(size_t)(rowA + 1) * NDB + ncol] = hi;
        }
    }
}

// ---------------- K3: partial per-row 4096-bin histograms (8 blocks/row) ----------------
__global__ void __launch_bounds__(512) k3_hist() {
    __shared__ unsigned int h[4096];
    int row  = blockIdx.y;
    int part = blockIdx.x;
    for (int i = threadIdx.x; i < 4096; i += 512) h[i] = 0u;
    __syncthreads();
    const uint4* Sp = (const uint4*)&g_S[(size_t)row * NDB] + (size_t)part * VPB;
#pragma unroll 2
    for (int i = threadIdx.x; i < VPB; i += 512) {
        uint4 v = Sp[i];
        atomicAdd(&h[v.x >> 20], 1u);
        atomicAdd(&h[v.y >> 20], 1u);
        atomicAdd(&h[v.z >> 20], 1u);
        atomicAdd(&h[v.w >> 20], 1u);
    }
    __syncthreads();
    unsigned int* gh = &g_hist[row * 4096];
    for (int i = threadIdx.x; i < 4096; i += 512)
        if (h[i]) atomicAdd(&gh[i], h[i]);
}

// ---------------- K3b: parallel suffix-scan of row hist -> d1, need ----------------
__global__ void __launch_bounds__(256) k3b_scan() {
    __shared__ unsigned int part[256];
    int row = blockIdx.x;
    int t = threadIdx.x;
    const unsigned int* gh = &g_hist[row * 4096];
    unsigned int loc[16];
    unsigned int s = 0;
#pragma unroll
    for (int j = 0; j < 16; j++) { loc[j] = gh[t * 16 + j]; s += loc[j]; }
    part[t] = s;
    __syncthreads();
    // inclusive suffix scan over 256 partials
    for (int off = 1; off < 256; off <<= 1) {
        unsigned int add = (t + off < 256) ? part[t + off] : 0u;
        __syncthreads();
        part[t] += add;
        __syncthreads();
    }
    unsigned int sAbove = (t < 255) ? part[t + 1] : 0u;   // suffix starting at (t+1)*16
    if (part[t] >= KSEL && sAbove < KSEL) {
        unsigned int cum = sAbove;
        for (int j = 15; j >= 0; j--) {
            cum += loc[j];
            if (cum >= KSEL) {
                g_d1[row]   = t * 16 + j;
                g_need[row] = KSEL - (int)(cum - loc[j]);
                break;
            }
        }
    }
}

// ---------------- K4: compact boundary candidates + label-count above (8 blocks/row) ----------------
__global__ void __launch_bounds__(512) k4_compact(const int* __restrict__ labels) {
    __shared__ unsigned int lh[NCLS];
    __shared__ int s_is64;
    int row  = blockIdx.y;
    int part = blockIdx.x;
    int d1   = g_d1[row];
    if (threadIdx.x < NCLS) lh[threadIdx.x] = 0u;
    if (threadIdx.x == 0) s_is64 = probe_is64(labels);
    __syncthreads();
    int is64 = s_is64;

    const uint4* Sp = (const uint4*)&g_S[(size_t)row * NDB] + (size_t)part * VPB;
    unsigned long long* cp = &g_cand[(size_t)row * NDB];
    int nbase = part * (VPB * 4);
#pragma unroll 2
    for (int i = threadIdx.x; i < VPB; i += 512) {
        uint4 v = Sp[i];
        int n0 = nbase + i * 4;
#pragma unroll
        for (int e = 0; e < 4; e++) {
            unsigned int mk = (&v.x)[e];
            int top = (int)(mk >> 20);
            if (top > d1) {
                int l = ldlabel(labels, n0 + e, is64);
                if (l >= 0 && l < NCLS) atomicAdd(&lh[l], 1u);
            } else if (top == d1) {
                unsigned int p = atomicAdd(&g_candCnt[row], 1u);
                cp[p] = ((unsigned long long)(mk & 0xFFFFFu) << 17) |
                        (unsigned long long)(unsigned int)(131071 - (n0 + e));
            }
        }
    }
    __syncthreads();
    if (threadIdx.x < NCLS && lh[threadIdx.x])
        atomicAdd(&g_counts[row * NCLS + threadIdx.x], lh[threadIdx.x]);
}

// ---------------- K5: exact 3-stage radix select (parallel scans) + finalize ----------------
__global__ void __launch_bounds__(512) k5_select(const int* __restrict__ labels,
                                                 float* __restrict__ out) {
    __shared__ unsigned int h[8192];
    __shared__ unsigned int part[512];
    __shared__ unsigned int lh[NCLS];
    __shared__ int s_dig, s_need, s_is64;
    int b = blockIdx.x;
    int t = threadIdx.x;
    int need = g_need[b];
    unsigned int cc = g_candCnt[b];
    const unsigned long long* cp = &g_cand[(size_t)b * NDB];

    if (t == 0) s_is64 = probe_is64(labels);

    const int shifts[3] = {24, 12, 0};
    const int nbits[3]  = {13, 12, 12};
    unsigned long long prefix = 0ull;

    for (int s = 0; s < 3; s++) {
        int sh = shifts[s];
        int nb = 1 << nbits[s];
        int ch = nb >> 9;                     // bins per thread (16 or 8)
        unsigned long long pmask = ~(((1ull << (sh + nbits[s])) - 1ull));
        for (int i = t; i < nb; i += 512) h[i] = 0u;
        __syncthreads();
        for (unsigned int i = t; i < cc; i += 512) {
            unsigned long long cv = cp[i];
            if ((cv & pmask) == prefix)
                atomicAdd(&h[(unsigned int)(cv >> sh) & (nb - 1)], 1u);
        }
        __syncthreads();
        unsigned int loc = 0;
        for (int j = 0; j < ch; j++) loc += h[t * ch + j];
        part[t] = loc;
        __syncthreads();
        for (int off = 1; off < 512; off <<= 1) {
            unsigned int add = (t + off < 512) ? part[t + off] : 0u;
            __syncthreads();
            part[t] += add;
            __syncthreads();
        }
        unsigned int sAbove = (t < 511) ? part[t + 1] : 0u;
        if ((int)part[t] >= need && (int)sAbove < need) {
            unsigned int cum = sAbove;
            for (int j = ch - 1; j >= 0; j--) {
                cum += h[t * ch + j];
                if ((int)cum >= need) {
                    s_dig  = t * ch + j;
                    s_need = need - (int)(cum - h[t * ch + j]);
                    break;
                }
            }
        }
        __syncthreads();
        prefix |= ((unsigned long long)s_dig) << sh;
        need = s_need;
        __syncthreads();
    }

    if (t < NCLS) lh[t] = 0u;
    __syncthreads();
    int is64 = s_is64;
    for (unsigned int i = t; i < cc; i += 512) {
        unsigned long long cv = cp[i];
        if (cv >= prefix) {
            int idx = 131071 - (int)(cv & 0x1FFFFull);
            if (idx >= 0 && idx < NDB) {
                int l = ldlabel(labels, idx, is64);
                if (l >= 0 && l < NCLS) atomicAdd(&lh[l], 1u);
            }
        }
    }
    __syncthreads();
    if (t < NCLS) {
        unsigned int tot = g_counts[b * NCLS + t] + lh[t];
        out[b * NCLS + t] = (float)tot * (1.0f / (float)KSEL);
    }
}

// ---------------- launch ----------------
extern "C" void kernel_launch(void* const* d_in, const int* in_sizes, int n_in,
                              void* d_out, int out_size) {
    const float* x      = (const float*)d_in[0];
    const float* W      = (const float*)d_in[1];
    const float* codes  = (const float*)d_in[2];
    const int*   labels = (const int*)d_in[3];
    float*       out    = (float*)d_out;

    void *p_hist, *p_counts, *p_cc;
    cudaGetSymbolAddress(&p_hist,   g_hist);
    cudaGetSymbolAddress(&p_counts, g_counts);
    cudaGetSymbolAddress(&p_cc,     g_candCnt);
    cudaMemsetAsync(p_hist,   0, sizeof(unsigned int) * NROWS * 4096);
    cudaMemsetAsync(p_counts, 0, sizeof(unsigned int) * NROWS * NCLS);
    cudaMemsetAsync(p_cc,     0, sizeof(unsigned int) * NROWS);

    k1_proj<<<NROWS, 256>>>(x, W);
    dim3 g2((NDB + 127) / 128, NROWS / 64);
    k2_gemm<<<g2, 256>>>(codes);
    dim3 g3(SPLIT, NROWS);
    k3_hist<<<g3, 512>>>();
    k3b_scan<<<NROWS, 256>>>();
    k4_compact<<<g3, 512>>>(labels);
    k5_select<<<NROWS, 512>>>(labels, out);
}

// round 6
// speedup vs baseline: 3.3873x; 1.0496x over previous
#include <cuda_runtime.h>
#include <cstdint>

#define NROWS 256
#define NDB   100000
#define DIM   64
#define XDIM  2048
#define NCLS  100
#define KSEL  1000
#define SPLIT 5
#define VP16  2500           // uint4 (8 u16) vectors per (row,part): 100000/8/5

// ---------------- static device scratch ----------------
__device__ float              g_outm[NROWS * DIM];
__device__ unsigned int       g_S[(size_t)NROWS * NDB];                 // 102.4 MB full keys
__device__ unsigned short     g_T16[(size_t)NROWS * NDB];               // 51.2 MB top-16 keys
__device__ unsigned long long g_cand[(size_t)NROWS * NDB];
__device__ unsigned int       g_hist[NROWS * 4096];
__device__ int                g_d1[NROWS];
__device__ int                g_need[NROWS];
__device__ unsigned int       g_candCnt[NROWS];
__device__ unsigned int       g_counts[NROWS * NCLS];

// ---------------- helpers ----------------
__device__ __forceinline__ unsigned int mkey(float f) {
    unsigned int u = __float_as_uint(f);
    return (u & 0x80000000u) ? ~u : (u | 0x80000000u);
}
__device__ __forceinline__ unsigned long long pk(float lo, float hi) {
    unsigned long long r;
    asm("mov.b64 %0, {%1,%2};" : "=l"(r)
        : "r"(__float_as_uint(lo)), "r"(__float_as_uint(hi)));
    return r;
}
__device__ __forceinline__ float f32lo(unsigned long long v) { return __uint_as_float((unsigned int)v); }
__device__ __forceinline__ float f32hi(unsigned long long v) { return __uint_as_float((unsigned int)(v >> 32)); }
__device__ __forceinline__ void fma2(unsigned long long& d, unsigned long long a, unsigned long long b) {
    asm("fma.rn.f32x2 %0, %1, %2, %0;" : "+l"(d) : "l"(a), "l"(b));
}
__device__ __forceinline__ int probe_is64(const int* L) {
    int s = 0;
#pragma unroll
    for (int i = 1; i < 129; i += 2) s |= L[i];
    return (s == 0) ? 1 : 0;
}
__device__ __forceinline__ int ldlabel(const int* L, int n, int is64) {
    return is64 ? L[(size_t)2 * n] : L[n];
}

// ---------------- K1: out = x @ W ----------------
__global__ void __launch_bounds__(256) k1_proj(const float* __restrict__ x,
                                               const float* __restrict__ W) {
    __shared__ __align__(16) float xs[XDIM];
    __shared__ float part[4][DIM];
    int b = blockIdx.x;
    const float4* xr = (const float4*)(x + (size_t)b * XDIM);
    for (int i = threadIdx.x; i < XDIM / 4; i += 256)
        ((float4*)xs)[i] = xr[i];
    __syncthreads();
    int j = threadIdx.x & 63;
    int p = threadIdx.x >> 6;
    const float* Wp = W + (size_t)(p * 512) * DIM + j;
    const float* xp = xs + p * 512;
    float a0 = 0.f, a1 = 0.f, a2 = 0.f, a3 = 0.f;
#pragma unroll 4
    for (int k = 0; k < 128; k++) {
        a0 += xp[k]       * Wp[(size_t)(k)       * DIM];
        a1 += xp[k + 128] * Wp[(size_t)(k + 128) * DIM];
        a2 += xp[k + 256] * Wp[(size_t)(k + 256) * DIM];
        a3 += xp[k + 384] * Wp[(size_t)(k + 384) * DIM];
    }
    part[p][j] = (a0 + a1) + (a2 + a3);
    __syncthreads();
    if (threadIdx.x < DIM)
        g_outm[b * DIM + threadIdx.x] =
            (part[0][threadIdx.x] + part[1][threadIdx.x]) +
            (part[2][threadIdx.x] + part[3][threadIdx.x]);
}

// ---------------- K2: keys = mkey(out @ codes^T); emits g_S + g_T16 ----------------
// grid: x = row-tiles (4), y = col-tiles (782)  -> B col-tile reused from L2
__global__ void __launch_bounds__(256, 3) k2_gemm(const float* __restrict__ codes) {
    __shared__ __align__(16) float As[64 * 64];
    __shared__ __align__(16) float Bs[64 * 128];
    const int tid  = threadIdx.x;
    const int row0 = blockIdx.x << 6;
    const int col0 = blockIdx.y << 7;
#pragma unroll
    for (int t = 0; t < 4; t++) {
        int e  = tid + t * 256;
        int i  = e >> 4;
        int k4 = (e & 15) << 2;
        float4 v = *(const float4*)&g_outm[((row0 + i) << 6) + k4];
#pragma unroll
        for (int j = 0; j < 4; j++) {
            int k = k4 + j;
            As[(k << 6) + ((((i >> 1) ^ (k & 31)) << 1) | (i & 1))] = (&v.x)[j];
        }
    }
#pragma unroll
    for (int t = 0; t < 8; t++) {
        int e  = tid + t * 256;
        int n  = e >> 4;
        int k4 = (e & 15) << 2;
        int gn = col0 + n;
        float4 v = make_float4(0.f, 0.f, 0.f, 0.f);
        if (gn < NDB) v = *(const float4*)&codes[((size_t)gn << 6) + k4];
#pragma unroll
        for (int j = 0; j < 4; j++) {
            int k = k4 + j;
            Bs[(k << 7) + ((((n >> 2) ^ (k & 31)) << 2) | (n & 3))] = (&v.x)[j];
        }
    }
    __syncthreads();

    const int r = tid >> 5;
    const int c = tid & 31;
    unsigned long long acc[4][4];
#pragma unroll
    for (int p = 0; p < 4; p++)
#pragma unroll
        for (int j = 0; j < 4; j++) acc[p][j] = 0ull;

#pragma unroll 4
    for (int k = 0; k < 64; k++) {
        int kb = k & 31;
        float4 bv = *(const float4*)&Bs[(k << 7) + ((c ^ kb) << 2)];
        unsigned long long b0 = pk(bv.x, bv.x);
        unsigned long long b1 = pk(bv.y, bv.y);
        unsigned long long b2 = pk(bv.z, bv.z);
        unsigned long long b3 = pk(bv.w, bv.w);
#pragma unroll
        for (int p = 0; p < 4; p++) {
            int grp = (r << 2) + p;
            float2 a = *(const float2*)&As[(k << 6) + ((grp ^ kb) << 1)];
            unsigned long long av = pk(a.x, a.y);
            fma2(acc[p][0], av, b0);
            fma2(acc[p][1], av, b1);
            fma2(acc[p][2], av, b2);
            fma2(acc[p][3], av, b3);
        }
    }

    int ncol = col0 + (c << 2);
    if (ncol < NDB) {
#pragma unroll
        for (int p = 0; p < 4; p++) {
            int rowA = row0 + (r << 3) + (p << 1);
            uint4 lo, hi;
            lo.x = mkey(f32lo(acc[p][0])); hi.x = mkey(f32hi(acc[p][0]));
            lo.y = mkey(f32lo(acc[p][1])); hi.y = mkey(f32hi(acc[p][1]));
            lo.z = mkey(f32lo(acc[p][2])); hi.z = mkey(f32hi(acc[p][2]));
            lo.w = mkey(f32lo(acc[p][3])); hi.w = mkey(f32hi(acc[p][3]));
            *(uint4*)&g_S[(size_t)rowA * NDB + ncol]       = lo;
            *(uint4*)&g_S[(size_t)(rowA + 1) * NDB + ncol] = hi;
            ushort4 tl, th;
            tl.x = (unsigned short)(lo.x >> 16); th.x = (unsigned short)(hi.x >> 16);
            tl.y = (unsigned short)(lo.y >> 16); th.y = (unsigned short)(hi.y >> 16);
            tl.z = (unsigned short)(lo.z >> 16); th.z = (unsigned short)(hi.z >> 16);
            tl.w = (unsigned short)(lo.w >> 16); th.w = (unsigned short)(hi.w >> 16);
            *(ushort4*)&g_T16[(size_t)rowA * NDB + ncol]       = tl;
            *(ushort4*)&g_T16[(size_t)(rowA + 1) * NDB + ncol] = th;
        }
    }
}

// ---------------- K3: per-row 4096-bin histograms from g_T16 (5 blocks/row) ----------------
__global__ void __launch_bounds__(512) k3_hist() {
    __shared__ unsigned int h[4096];
    int row  = blockIdx.y;
    int part = blockIdx.x;
    for (int i = threadIdx.x; i < 4096; i += 512) h[i] = 0u;
    __syncthreads();
    const uint4* Tp = (const uint4*)(g_T16 + (size_t)row * NDB) + (size_t)part * VP16;
#pragma unroll 2
    for (int i = threadIdx.x; i < VP16; i += 512) {
        uint4 v = Tp[i];
        atomicAdd(&h[(v.x & 0xFFFFu) >> 4], 1u);
        atomicAdd(&h[(v.x >> 20)],          1u);
        atomicAdd(&h[(v.y & 0xFFFFu) >> 4], 1u);
        atomicAdd(&h[(v.y >> 20)],          1u);
        atomicAdd(&h[(v.z & 0xFFFFu) >> 4], 1u);
        atomicAdd(&h[(v.z >> 20)],          1u);
        atomicAdd(&h[(v.w & 0xFFFFu) >> 4], 1u);
        atomicAdd(&h[(v.w >> 20)],          1u);
    }
    __syncthreads();
    unsigned int* gh = &g_hist[row * 4096];
    for (int i = threadIdx.x; i < 4096; i += 512)
        if (h[i]) atomicAdd(&gh[i], h[i]);
}

// ---------------- K3b: parallel suffix scan -> d1, need ----------------
__global__ void __launch_bounds__(256) k3b_scan() {
    __shared__ unsigned int part[256];
    int row = blockIdx.x;
    int t = threadIdx.x;
    const unsigned int* gh = &g_hist[row * 4096];
    unsigned int loc[16];
    unsigned int s = 0;
#pragma unroll
    for (int j = 0; j < 16; j++) { loc[j] = gh[t * 16 + j]; s += loc[j]; }
    part[t] = s;
    __syncthreads();
    for (int off = 1; off < 256; off <<= 1) {
        unsigned int add = (t + off < 256) ? part[t + off] : 0u;
        __syncthreads();
        part[t] += add;
        __syncthreads();
    }
    unsigned int sAbove = (t < 255) ? part[t + 1] : 0u;
    if (part[t] >= KSEL && sAbove < KSEL) {
        unsigned int cum = sAbove;
        for (int j = 15; j >= 0; j--) {
            cum += loc[j];
            if (cum >= KSEL) {
                g_d1[row]   = t * 16 + j;
                g_need[row] = KSEL - (int)(cum - loc[j]);
                break;
            }
        }
    }
}

// ---------------- K4: classify from g_T16; fetch full key only for boundary ----------------
__global__ void __launch_bounds__(512) k4_compact(const int* __restrict__ labels) {
    __shared__ unsigned int lh[NCLS];
    __shared__ int s_is64;
    int row  = blockIdx.y;
    int part = blockIdx.x;
    int d1   = g_d1[row];
    int lane = threadIdx.x & 31;
    if (threadIdx.x < NCLS) lh[threadIdx.x] = 0u;
    if (threadIdx.x == 0) s_is64 = probe_is64(labels);
    __syncthreads();
    int is64 = s_is64;

    const uint4* Tp = (const uint4*)(g_T16 + (size_t)row * NDB) + (size_t)part * VP16;
    const unsigned int* Sp = &g_S[(size_t)row * NDB];
    unsigned long long* cp = &g_cand[(size_t)row * NDB];
    int nbase = part * (VP16 * 8);

    for (int i0 = 0; i0 < VP16; i0 += 512) {        // uniform trip count for ballots
        int i = i0 + threadIdx.x;
        bool valid = (i < VP16);
        uint4 v = make_uint4(0, 0, 0, 0);
        if (valid) v = Tp[i];
        unsigned short s8[8];
        s8[0] = (unsigned short)(v.x & 0xFFFFu); s8[1] = (unsigned short)(v.x >> 16);
        s8[2] = (unsigned short)(v.y & 0xFFFFu); s8[3] = (unsigned short)(v.y >> 16);
        s8[4] = (unsigned short)(v.z & 0xFFFFu); s8[5] = (unsigned short)(v.z >> 16);
        s8[6] = (unsigned short)(v.w & 0xFFFFu); s8[7] = (unsigned short)(v.w >> 16);
        int n0 = nbase + i * 8;
#pragma unroll
        for (int e = 0; e < 8; e++) {
            int top = (int)(s8[e] >> 4);
            bool above = valid && (top > d1);
            bool bound = valid && (top == d1);
            if (above) {
                int l = ldlabel(labels, n0 + e, is64);
                if (l >= 0 && l < NCLS) atomicAdd(&lh[l], 1u);
            }
            unsigned int m = __ballot_sync(0xFFFFFFFFu, bound);
            if (m) {
                int leader = __ffs(m) - 1;
                unsigned int base = 0;
                if (lane == leader) base = atomicAdd(&g_candCnt[row], (unsigned int)__popc(m));
                base = __shfl_sync(0xFFFFFFFFu, base, leader);
                if (bound) {
                    unsigned int mk = Sp[n0 + e];
                    int rank = __popc(m & ((1u << lane) - 1u));
                    cp[base + rank] =
                        ((unsigned long long)(mk & 0xFFFFFu) << 17) |
                        (unsigned long long)(unsigned int)(131071 - (n0 + e));
                }
            }
        }
    }
    __syncthreads();
    if (threadIdx.x < NCLS && lh[threadIdx.x])
        atomicAdd(&g_counts[row * NCLS + threadIdx.x], lh[threadIdx.x]);
}

// ---------------- K5: exact 3-stage radix select + finalize ----------------
__global__ void __launch_bounds__(512) k5_select(const int* __restrict__ labels,
                                                 float* __restrict__ out) {
    __shared__ unsigned int h[8192];
    __shared__ unsigned int part[512];
    __shared__ unsigned int lh[NCLS];
    __shared__ int s_dig, s_need, s_is64;
    int b = blockIdx.x;
    int t = threadIdx.x;
    int need = g_need[b];
    unsigned int cc = g_candCnt[b];
    const unsigned long long* cp = &g_cand[(size_t)b * NDB];

    if (t == 0) s_is64 = probe_is64(labels);

    const int shifts[3] = {24, 12, 0};
    const int nbits[3]  = {13, 12, 12};
    unsigned long long prefix = 0ull;

    for (int s = 0; s < 3; s++) {
        int sh = shifts[s];
        int nb = 1 << nbits[s];
        int ch = nb >> 9;
        unsigned long long pmask = ~(((1ull << (sh + nbits[s])) - 1ull));
        for (int i = t; i < nb; i += 512) h[i] = 0u;
        __syncthreads();
        for (unsigned int i = t; i < cc; i += 512) {
            unsigned long long cv = cp[i];
            if ((cv & pmask) == prefix)
                atomicAdd(&h[(unsigned int)(cv >> sh) & (nb - 1)], 1u);
        }
        __syncthreads();
        unsigned int loc = 0;
        for (int j = 0; j < ch; j++) loc += h[t * ch + j];
        part[t] = loc;
        __syncthreads();
        for (int off = 1; off < 512; off <<= 1) {
            unsigned int add = (t + off < 512) ? part[t + off] : 0u;
            __syncthreads();
            part[t] += add;
            __syncthreads();
        }
        unsigned int sAbove = (t < 511) ? part[t + 1] : 0u;
        if ((int)part[t] >= need && (int)sAbove < need) {
            unsigned int cum = sAbove;
            for (int j = ch - 1; j >= 0; j--) {
                cum += h[t * ch + j];
                if ((int)cum >= need) {
                    s_dig  = t * ch + j;
                    s_need = need - (int)(cum - h[t * ch + j]);
                    break;
                }
            }
        }
        __syncthreads();
        prefix |= ((unsigned long long)s_dig) << sh;
        need = s_need;
        __syncthreads();
    }

    if (t < NCLS) lh[t] = 0u;
    __syncthreads();
    int is64 = s_is64;
    for (unsigned int i = t; i < cc; i += 512) {
        unsigned long long cv = cp[i];
        if (cv >= prefix) {
            int idx = 131071 - (int)(cv & 0x1FFFFull);
            if (idx >= 0 && idx < NDB) {
                int l = ldlabel(labels, idx, is64);
                if (l >= 0 && l < NCLS) atomicAdd(&lh[l], 1u);
            }
        }
    }
    __syncthreads();
    if (t < NCLS) {
        unsigned int tot = g_counts[b * NCLS + t] + lh[t];
        out[b * NCLS + t] = (float)tot * (1.0f / (float)KSEL);
    }
}

// ---------------- launch ----------------
extern "C" void kernel_launch(void* const* d_in, const int* in_sizes, int n_in,
                              void* d_out, int out_size) {
    const float* x      = (const float*)d_in[0];
    const float* W      = (const float*)d_in[1];
    const float* codes  = (const float*)d_in[2];
    const int*   labels = (const int*)d_in[3];
    float*       out    = (float*)d_out;

    void *p_hist, *p_counts, *p_cc;
    cudaGetSymbolAddress(&p_hist,   g_hist);
    cudaGetSymbolAddress(&p_counts, g_counts);
    cudaGetSymbolAddress(&p_cc,     g_candCnt);
    cudaMemsetAsync(p_hist,   0, sizeof(unsigned int) * NROWS * 4096);
    cudaMemsetAsync(p_counts, 0, sizeof(unsigned int) * NROWS * NCLS);
    cudaMemsetAsync(p_cc,     0, sizeof(unsigned int) * NROWS);

    k1_proj<<<NROWS, 256>>>(x, W);
    dim3 g2(NROWS / 64, (NDB + 127) / 128);
    k2_gemm<<<g2, 256>>>(codes);
    dim3 g3(SPLIT, NROWS);
    k3_hist<<<g3, 512>>>();
    k3b_scan<<<NROWS, 256>>>();
    k4_compact<<<g3, 512>>>(labels);
    k5_select<<<NROWS, 512>>>(labels, out);
}